// round 1
// baseline (speedup 1.0000x reference)
#include <cuda_runtime.h>
#include <math.h>

// ---------------------------------------------------------------------------
// Problem constants (fixed shapes)
// ---------------------------------------------------------------------------
constexpr int T  = 2048;
constexpr int B  = 4;
constexpr int E  = 1024;
constexpr int H  = 16;
constexpr int D  = 64;     // head dim
constexpr int BH = B * H;  // 64

constexpr size_t QKV_ELEMS  = (size_t)T * B * 3 * E;   // 25,165,824
constexpr size_t HEAD_ELEMS = (size_t)BH * T * D;      //  8,388,608
constexpr size_t OUT_ELEMS  = (size_t)T * B * E;       //  8,388,608
constexpr size_t ATTN_ELEMS = (size_t)BH * T * T;      // 268,435,456

// Scratch (allocation-free rule: __device__ globals)
__device__ float g_qkv[QKV_ELEMS];
__device__ float g_q  [HEAD_ELEMS];
__device__ float g_k  [HEAD_ELEMS];
__device__ float g_v  [HEAD_ELEMS];
__device__ float g_ctx[OUT_ELEMS];
__device__ float g_attn[ATTN_ELEMS];   // used only if attn is not part of d_out

// ---------------------------------------------------------------------------
// Generic TN GEMM:  C[m,n] = sum_k A[m,k] * Bw[n,k]  (+ bias[n])
// Tiles: 128x128, BK=8, 256 threads, 8x8 microtile per thread.
// Batched via blockIdx.z with element strides sA/sB/sC.
// causal!=0: skip tiles with bx > by (fully-masked score tiles).
// Requires: M,N multiples of 128 (grid sized accordingly), K multiple of 8,
//           A/B rows 16B-aligned (lda,ldb multiples of 4). All hold here.
// ---------------------------------------------------------------------------
__global__ __launch_bounds__(256) void gemm_tn(
    const float* __restrict__ A, const float* __restrict__ Bw,
    const float* __restrict__ bias, float* __restrict__ C,
    int K, int lda, int ldb, int ldc,
    size_t sA, size_t sB, size_t sC, int causal)
{
    const int bx = blockIdx.x, by = blockIdx.y, bz = blockIdx.z;
    if (causal && bx > by) return;
    A  += sA * (size_t)bz;
    Bw += sB * (size_t)bz;
    C  += sC * (size_t)bz;

    __shared__ __align__(16) float As[8][128];
    __shared__ __align__(16) float Bs[8][128];

    const int tid = threadIdx.x;
    const int lr  = tid >> 1;          // 0..127 : row within tile (load)
    const int lk  = (tid & 1) << 2;    // 0 or 4 : k offset (load)
    const int ty  = tid >> 4;          // 0..15
    const int tx  = tid & 15;          // 0..15

    const float* Ap = A  + (size_t)(by * 128 + lr) * lda + lk;
    const float* Bp = Bw + (size_t)(bx * 128 + lr) * ldb + lk;

    float acc[8][8];
#pragma unroll
    for (int i = 0; i < 8; i++)
#pragma unroll
        for (int j = 0; j < 8; j++) acc[i][j] = 0.f;

    for (int k0 = 0; k0 < K; k0 += 8) {
        float4 av = *(const float4*)(Ap + k0);
        float4 bv = *(const float4*)(Bp + k0);
        As[lk + 0][lr] = av.x; As[lk + 1][lr] = av.y;
        As[lk + 2][lr] = av.z; As[lk + 3][lr] = av.w;
        Bs[lk + 0][lr] = bv.x; Bs[lk + 1][lr] = bv.y;
        Bs[lk + 2][lr] = bv.z; Bs[lk + 3][lr] = bv.w;
        __syncthreads();
#pragma unroll
        for (int kk = 0; kk < 8; kk++) {
            float4 a0 = *(const float4*)&As[kk][ty * 8];
            float4 a1 = *(const float4*)&As[kk][ty * 8 + 4];
            float4 b0 = *(const float4*)&Bs[kk][tx * 8];
            float4 b1 = *(const float4*)&Bs[kk][tx * 8 + 4];
            float ar[8] = {a0.x, a0.y, a0.z, a0.w, a1.x, a1.y, a1.z, a1.w};
            float br[8] = {b0.x, b0.y, b0.z, b0.w, b1.x, b1.y, b1.z, b1.w};
#pragma unroll
            for (int i = 0; i < 8; i++)
#pragma unroll
                for (int j = 0; j < 8; j++)
                    acc[i][j] = fmaf(ar[i], br[j], acc[i][j]);
        }
        __syncthreads();
    }

    float bb[8];
#pragma unroll
    for (int j = 0; j < 8; j++)
        bb[j] = bias ? bias[bx * 128 + tx * 8 + j] : 0.f;

#pragma unroll
    for (int i = 0; i < 8; i++) {
        const int row = by * 128 + ty * 8 + i;
        float4 o0 = make_float4(acc[i][0] + bb[0], acc[i][1] + bb[1],
                                acc[i][2] + bb[2], acc[i][3] + bb[3]);
        float4 o1 = make_float4(acc[i][4] + bb[4], acc[i][5] + bb[5],
                                acc[i][6] + bb[6], acc[i][7] + bb[7]);
        *(float4*)&C[(size_t)row * ldc + bx * 128 + tx * 8]     = o0;
        *(float4*)&C[(size_t)row * ldc + bx * 128 + tx * 8 + 4] = o1;
    }
}

// ---------------------------------------------------------------------------
// RoPE + reshape:  qkv[T,B,3E] -> q/k/v [bh][t][d], RoPE on q,k, q *= D^-0.5
// One block per (t,b). 256 threads loop over 3E = 3072 features.
// ---------------------------------------------------------------------------
__global__ __launch_bounds__(256) void rope_kernel(
    const float* __restrict__ qkv, const float* __restrict__ pos,
    float* __restrict__ q, float* __restrict__ k, float* __restrict__ v)
{
    const int m = blockIdx.x;        // t*B + b
    const int t = m >> 2;            // B = 4
    const int b = m & 3;
    const size_t base = (size_t)m * (3 * E);

    for (int e = threadIdx.x; e < 3 * E; e += 256) {
        const int sec = e >> 10;         // 0=q 1=k 2=v
        const int r   = e & 1023;
        const int h   = r >> 6;
        const int d   = r & 63;
        const float val = qkv[base + e];
        const size_t oidx = (size_t)(b * H + h) * T * D + (size_t)t * D + d;
        if (sec == 2) {
            v[oidx] = val;
        } else {
            const float ang = pos[t * D + d];
            float c, s;
            sincosf(ang, &s, &c);
            const int pd = (d < 32) ? (e + 32) : (e - 32);
            const float other = qkv[base + pd];
            const float rot = (d < 32) ? -other : other;
            const float res = fmaf(val, c, rot * s);
            if (sec == 0) q[oidx] = res * 0.125f;   // * D^-0.5
            else          k[oidx] = res;
        }
    }
}

// ---------------------------------------------------------------------------
// Row softmax over raw scores, in place, causal.
// One block per (t, bh). Row cached in smem (8KB): 1 global read, 1 write.
// Also zero-fills the masked region s in (t, T).
// ---------------------------------------------------------------------------
__global__ __launch_bounds__(256) void softmax_kernel(float* __restrict__ attn)
{
    const int t  = blockIdx.x;
    const int bh = blockIdx.y;
    float* rowp = attn + (size_t)bh * T * T + (size_t)t * T;
    const int L = t + 1;

    __shared__ float row[T];
    __shared__ float red[8];
    const int tid = threadIdx.x;

    float m = -1e30f;
    for (int i = tid; i < L; i += 256) {
        const float x = rowp[i];
        row[i] = x;
        m = fmaxf(m, x);
    }
#pragma unroll
    for (int o = 16; o; o >>= 1) m = fmaxf(m, __shfl_xor_sync(0xffffffffu, m, o));
    if ((tid & 31) == 0) red[tid >> 5] = m;
    __syncthreads();
    m = red[0];
#pragma unroll
    for (int w = 1; w < 8; w++) m = fmaxf(m, red[w]);

    float sum = 0.f;
    for (int i = tid; i < L; i += 256) {
        const float e = __expf(row[i] - m);
        row[i] = e;
        sum += e;
    }
#pragma unroll
    for (int o = 16; o; o >>= 1) sum += __shfl_xor_sync(0xffffffffu, sum, o);
    __syncthreads();                  // red reuse
    if ((tid & 31) == 0) red[tid >> 5] = sum;
    __syncthreads();
    sum = 0.f;
#pragma unroll
    for (int w = 0; w < 8; w++) sum += red[w];
    const float inv = 1.f / sum;

    for (int i = tid; i < L; i += 256) rowp[i] = row[i] * inv;
    for (int i = L + tid; i < T; i += 256) rowp[i] = 0.f;
}

// ---------------------------------------------------------------------------
// ctx[t, b, h*D + d] = sum_s attn[bh][t][s] * v[bh][s][d]
// NN GEMM: 128x64 tile, BK=16, 256 threads, 8x4 microtile.
// Causal: K loop bounded by (by+1)*128 (attn is zero beyond t anyway).
// ---------------------------------------------------------------------------
__global__ __launch_bounds__(256) void ctx_kernel(
    const float* __restrict__ attn, const float* __restrict__ v,
    float* __restrict__ ctx)
{
    const int by = blockIdx.y;
    const int bh = blockIdx.z;
    const float* A  = attn + (size_t)bh * T * T;     // lda = T
    const float* Bv = v    + (size_t)bh * T * D;     // ldb = D
    const int zoff = (bh >> 4) * E + (bh & 15) * D;  // b*E + h*D

    __shared__ __align__(16) float As[16][128];
    __shared__ __align__(16) float Bs[16][64];

    const int tid = threadIdx.x;
    const int lr  = tid >> 1;            // 0..127
    const int lk  = (tid & 1) << 3;      // 0 or 8
    const int kb  = tid >> 4;            // 0..15
    const int nb  = (tid & 15) << 2;     // 0..60
    const int ty  = tid >> 4;            // 0..15
    const int tx  = tid & 15;            // 0..15

    float acc[8][4];
#pragma unroll
    for (int i = 0; i < 8; i++)
#pragma unroll
        for (int j = 0; j < 4; j++) acc[i][j] = 0.f;

    const int Kend = (by + 1) * 128;
    const float* Ap = A + (size_t)(by * 128 + lr) * T + lk;

    for (int k0 = 0; k0 < Kend; k0 += 16) {
        float4 av0 = *(const float4*)(Ap + k0);
        float4 av1 = *(const float4*)(Ap + k0 + 4);
        float4 bv  = *(const float4*)&Bv[(size_t)(k0 + kb) * D + nb];
        As[lk + 0][lr] = av0.x; As[lk + 1][lr] = av0.y;
        As[lk + 2][lr] = av0.z; As[lk + 3][lr] = av0.w;
        As[lk + 4][lr] = av1.x; As[lk + 5][lr] = av1.y;
        As[lk + 6][lr] = av1.z; As[lk + 7][lr] = av1.w;
        *(float4*)&Bs[kb][nb] = bv;
        __syncthreads();
#pragma unroll
        for (int kk = 0; kk < 16; kk++) {
            float4 a0 = *(const float4*)&As[kk][ty * 8];
            float4 a1 = *(const float4*)&As[kk][ty * 8 + 4];
            float4 b0 = *(const float4*)&Bs[kk][tx * 4];
            float ar[8] = {a0.x, a0.y, a0.z, a0.w, a1.x, a1.y, a1.z, a1.w};
            float br[4] = {b0.x, b0.y, b0.z, b0.w};
#pragma unroll
            for (int i = 0; i < 8; i++)
#pragma unroll
                for (int j = 0; j < 4; j++)
                    acc[i][j] = fmaf(ar[i], br[j], acc[i][j]);
        }
        __syncthreads();
    }

#pragma unroll
    for (int i = 0; i < 8; i++) {
        const int t = by * 128 + ty * 8 + i;
        *(float4*)&ctx[(size_t)t * (B * E) + zoff + tx * 4] =
            make_float4(acc[i][0], acc[i][1], acc[i][2], acc[i][3]);
    }
}

// ---------------------------------------------------------------------------
// Launch
// ---------------------------------------------------------------------------
extern "C" void kernel_launch(void* const* d_in, const int* in_sizes, int n_in,
                              void* d_out, int out_size)
{
    const float* input = (const float*)d_in[0];
    const float* pos   = (const float*)d_in[1];
    const float* in_w  = (const float*)d_in[2];
    const float* in_b  = (const float*)d_in[3];
    const float* out_w = (const float*)d_in[4];
    const float* out_b = (const float*)d_in[5];
    float* out = (float*)d_out;

    float *qkv, *q, *k, *v, *ctx, *attn_scratch;
    cudaGetSymbolAddress((void**)&qkv,          g_qkv);
    cudaGetSymbolAddress((void**)&q,            g_q);
    cudaGetSymbolAddress((void**)&k,            g_k);
    cudaGetSymbolAddress((void**)&v,            g_v);
    cudaGetSymbolAddress((void**)&ctx,          g_ctx);
    cudaGetSymbolAddress((void**)&attn_scratch, g_attn);

    // Reference returns (out, attn). If out_size covers both (flattened in
    // order), attn lives in d_out after out; otherwise attn goes to scratch.
    float* attn = ((size_t)out_size >= OUT_ELEMS + ATTN_ELEMS)
                      ? (out + OUT_ELEMS) : attn_scratch;

    // 1) fused QKV projection: [T*B, 3E] = input[T*B, E] @ in_w[3E, E]^T + b
    gemm_tn<<<dim3(3 * E / 128, T * B / 128, 1), 256>>>(
        input, in_w, in_b, qkv, E, E, E, 3 * E, 0, 0, 0, 0);

    // 2) RoPE + reshape to [bh][t][d]
    rope_kernel<<<T * B, 256>>>(qkv, pos, q, k, v);

    // 3) raw scores per head: attn[bh][t][s] = q_t . k_s  (causal tile skip)
    gemm_tn<<<dim3(T / 128, T / 128, BH), 256>>>(
        q, k, nullptr, attn, D, D, D, T,
        (size_t)T * D, (size_t)T * D, (size_t)T * T, 1);

    // 4) in-place causal softmax (+ zero the masked region)
    softmax_kernel<<<dim3(T, BH), 256>>>(attn);

    // 5) ctx = attn @ v, written directly in [t, b, e] layout
    ctx_kernel<<<dim3(1, T / 128, BH), 256>>>(attn, v, ctx);

    // 6) output projection: out[T*B, E] = ctx @ out_w^T + out_b
    gemm_tn<<<dim3(E / 128, T * B / 128, 1), 256>>>(
        ctx, out_w, out_b, out, E, E, E, E, 0, 0, 0, 0);
}

// round 3
// speedup vs baseline: 2.8798x; 2.8798x over previous
#include <cuda_runtime.h>
#include <cuda_bf16.h>
#include <math.h>
#include <stdint.h>

// ---------------------------------------------------------------------------
// Problem constants (fixed shapes)
// ---------------------------------------------------------------------------
constexpr int T  = 2048;
constexpr int B  = 4;
constexpr int E  = 1024;
constexpr int H  = 16;
constexpr int D  = 64;     // head dim
constexpr int BH = B * H;  // 64

constexpr size_t QKV_ELEMS  = (size_t)T * B * 3 * E;
constexpr size_t HEAD_ELEMS = (size_t)BH * T * D;
constexpr size_t OUT_ELEMS  = (size_t)T * B * E;
constexpr size_t ATTN_ELEMS = (size_t)BH * T * T;

__device__ float g_qkv[QKV_ELEMS];
__device__ float g_q  [HEAD_ELEMS];
__device__ float g_k  [HEAD_ELEMS];
__device__ float g_vT [HEAD_ELEMS];   // [bh][d][t]
__device__ float g_ctx[OUT_ELEMS];
__device__ float g_attn[ATTN_ELEMS];

// ---------------------------------------------------------------------------
// Warp-MMA helpers (sm_80+ path; no 'a'-suffix features)
// ---------------------------------------------------------------------------
__device__ __forceinline__ uint32_t smem_u32(const void* p) {
    uint32_t a;
    asm("{ .reg .u64 t; cvta.to.shared.u64 t, %1; cvt.u32.u64 %0, t; }"
        : "=r"(a) : "l"(p));
    return a;
}
__device__ __forceinline__ void ldm_x4(uint32_t& r0, uint32_t& r1,
                                       uint32_t& r2, uint32_t& r3, uint32_t addr) {
    asm volatile("ldmatrix.sync.aligned.m8n8.x4.shared.b16 {%0,%1,%2,%3}, [%4];"
                 : "=r"(r0), "=r"(r1), "=r"(r2), "=r"(r3) : "r"(addr));
}
__device__ __forceinline__ void mma16816(float* c, const uint32_t* a,
                                         const uint32_t* b) {
    asm volatile(
        "mma.sync.aligned.m16n8k16.row.col.f32.bf16.bf16.f32 "
        "{%0,%1,%2,%3}, {%4,%5,%6,%7}, {%8,%9}, {%0,%1,%2,%3};"
        : "+f"(c[0]), "+f"(c[1]), "+f"(c[2]), "+f"(c[3])
        : "r"(a[0]), "r"(a[1]), "r"(a[2]), "r"(a[3]), "r"(b[0]), "r"(b[1]));
}
__device__ __forceinline__ uint32_t packbf2(__nv_bfloat16 a, __nv_bfloat16 b) {
    __nv_bfloat162 t(a, b);
    return *reinterpret_cast<uint32_t*>(&t);
}
__device__ __forceinline__ void split_bf(float x, __nv_bfloat16& h, __nv_bfloat16& l) {
    h = __float2bfloat16(x);
    l = __float2bfloat16(x - __bfloat162float(h));
}

// ---------------------------------------------------------------------------
// bf16x3 TN GEMM via mma.sync:  C[m,n] = sum_k A[m,k]*Bw[n,k] (+bias[n])
// Block tile 128 x TILE_N, K-chunk 32 (fp32). 256 threads = 8 warps (2m x 4n).
// mode: 0 = plain, 1 = causal tile skip (bx>by), 2 = K bounded by (by+1)*128.
// Requires: M mult 128, N mult TILE_N, K mult 32, lda/ldb mult 4.
// ---------------------------------------------------------------------------
template <int TILE_N>
__global__ __launch_bounds__(256) void mma_gemm(
    const float* __restrict__ A, const float* __restrict__ Bw,
    const float* __restrict__ bias, float* __restrict__ C,
    int K, int lda, int ldb, int ldc,
    size_t sA, size_t sB, size_t sC, int mode)
{
    const int bx = blockIdx.x, by = blockIdx.y, bz = blockIdx.z;
    if (mode == 1 && bx > by) return;
    A  += sA * (size_t)bz;
    Bw += sB * (size_t)bz;
    C  += sC * (size_t)bz;
    const int Keff = (mode == 2) ? (by + 1) * 128 : K;

    constexpr int ST   = 40;            // bf16 per smem row (80B, ldmatrix-clean)
    constexpr int WN   = TILE_N / 4;    // warp n-extent: 32 or 16
    constexpr int NF   = WN / 8;        // n-frags per warp: 4 or 2
    constexpr int WN16 = WN / 16;       // ldmatrix.x4 groups for B: 2 or 1
    constexpr int BI   = TILE_N * 8 / 256;  // B float4 loads/thread: 4 or 2

    __shared__ __align__(16) __nv_bfloat16 sAh[128 * ST];
    __shared__ __align__(16) __nv_bfloat16 sAl[128 * ST];
    __shared__ __align__(16) __nv_bfloat16 sBh[TILE_N * ST];
    __shared__ __align__(16) __nv_bfloat16 sBl[TILE_N * ST];

    const int tid  = threadIdx.x;
    const int lane = tid & 31;
    const int wid  = tid >> 5;
    const int wm   = wid & 1;           // 0..1  (64 rows each)
    const int wn   = wid >> 1;          // 0..3  (WN cols each)

    // ldmatrix per-lane addressing: rows fm + (lane&15), col fk + 8*(lane>>4)
    const int lr16 = lane & 15;
    const int kc8  = (lane >> 4) << 3;
    const uint32_t uAh = smem_u32(sAh), uAl = smem_u32(sAl);
    const uint32_t uBh = smem_u32(sBh), uBl = smem_u32(sBl);

    float acc[4][NF][4] = {};

    const int nch = Keff >> 5;
    float4 aR[4], bR[BI];

    // prologue: prefetch chunk 0
#pragma unroll
    for (int i = 0; i < 4; i++) {
        const int slot = tid + i * 256, r = slot >> 3, c4 = slot & 7;
        aR[i] = *(const float4*)(A + (size_t)(by * 128 + r) * lda + c4 * 4);
    }
#pragma unroll
    for (int i = 0; i < BI; i++) {
        const int slot = tid + i * 256, r = slot >> 3, c4 = slot & 7;
        bR[i] = *(const float4*)(Bw + (size_t)(bx * TILE_N + r) * ldb + c4 * 4);
    }

    for (int ch = 0; ch < nch; ch++) {
        // convert + store to smem
#pragma unroll
        for (int i = 0; i < 4; i++) {
            const int slot = tid + i * 256, r = slot >> 3, c4 = slot & 7;
            __nv_bfloat16 h0,h1,h2,h3,l0,l1,l2,l3;
            split_bf(aR[i].x,h0,l0); split_bf(aR[i].y,h1,l1);
            split_bf(aR[i].z,h2,l2); split_bf(aR[i].w,h3,l3);
            *(uint2*)&sAh[r * ST + c4 * 4] = make_uint2(packbf2(h0,h1), packbf2(h2,h3));
            *(uint2*)&sAl[r * ST + c4 * 4] = make_uint2(packbf2(l0,l1), packbf2(l2,l3));
        }
#pragma unroll
        for (int i = 0; i < BI; i++) {
            const int slot = tid + i * 256, r = slot >> 3, c4 = slot & 7;
            __nv_bfloat16 h0,h1,h2,h3,l0,l1,l2,l3;
            split_bf(bR[i].x,h0,l0); split_bf(bR[i].y,h1,l1);
            split_bf(bR[i].z,h2,l2); split_bf(bR[i].w,h3,l3);
            *(uint2*)&sBh[r * ST + c4 * 4] = make_uint2(packbf2(h0,h1), packbf2(h2,h3));
            *(uint2*)&sBl[r * ST + c4 * 4] = make_uint2(packbf2(l0,l1), packbf2(l2,l3));
        }
        __syncthreads();

        // prefetch next chunk into regs (overlaps with MMA below)
        if (ch + 1 < nch) {
            const int k0 = (ch + 1) << 5;
#pragma unroll
            for (int i = 0; i < 4; i++) {
                const int slot = tid + i * 256, r = slot >> 3, c4 = slot & 7;
                aR[i] = *(const float4*)(A + (size_t)(by * 128 + r) * lda + k0 + c4 * 4);
            }
#pragma unroll
            for (int i = 0; i < BI; i++) {
                const int slot = tid + i * 256, r = slot >> 3, c4 = slot & 7;
                bR[i] = *(const float4*)(Bw + (size_t)(bx * TILE_N + r) * ldb + k0 + c4 * 4);
            }
        }

        // MMA over this chunk: 2 k16 steps
#pragma unroll
        for (int ks = 0; ks < 2; ks++) {
            const int fk = ks * 16;
            uint32_t bh[NF][2], bl[NF][2];
#pragma unroll
            for (int jj = 0; jj < WN16; jj++) {
                const uint32_t off =
                    (uint32_t)((wn * WN + jj * 16 + lr16) * ST + fk + kc8) * 2;
                ldm_x4(bh[2*jj][0], bh[2*jj+1][0], bh[2*jj][1], bh[2*jj+1][1], uBh + off);
                ldm_x4(bl[2*jj][0], bl[2*jj+1][0], bl[2*jj][1], bl[2*jj+1][1], uBl + off);
            }
#pragma unroll
            for (int i = 0; i < 4; i++) {
                const uint32_t off =
                    (uint32_t)((wm * 64 + i * 16 + lr16) * ST + fk + kc8) * 2;
                uint32_t ah[4], al[4];
                ldm_x4(ah[0], ah[1], ah[2], ah[3], uAh + off);
                ldm_x4(al[0], al[1], al[2], al[3], uAl + off);
#pragma unroll
                for (int j = 0; j < NF; j++) {
                    mma16816(acc[i][j], ah, bh[j]);
                    mma16816(acc[i][j], ah, bl[j]);
                    mma16816(acc[i][j], al, bh[j]);
                }
            }
        }
        __syncthreads();
    }

    // epilogue
    const int g = lane >> 2, t4 = lane & 3;
#pragma unroll
    for (int i = 0; i < 4; i++) {
#pragma unroll
        for (int j = 0; j < NF; j++) {
            const int row = by * 128 + wm * 64 + i * 16 + g;
            const int col = bx * TILE_N + wn * WN + j * 8 + t4 * 2;
            float b0 = 0.f, b1 = 0.f;
            if (bias) { b0 = bias[col]; b1 = bias[col + 1]; }
            *(float2*)&C[(size_t)row * ldc + col] =
                make_float2(acc[i][j][0] + b0, acc[i][j][1] + b1);
            *(float2*)&C[(size_t)(row + 8) * ldc + col] =
                make_float2(acc[i][j][2] + b0, acc[i][j][3] + b1);
        }
    }
}

// ---------------------------------------------------------------------------
// RoPE + reshape:  qkv[T,B,3E] -> q/k [bh][t][d] (RoPE, q*=D^-0.5),
//                  v -> vT [bh][d][t] (transposed for the ctx TN GEMM).
// ---------------------------------------------------------------------------
__global__ __launch_bounds__(256) void rope_kernel(
    const float* __restrict__ qkv, const float* __restrict__ pos,
    float* __restrict__ q, float* __restrict__ k, float* __restrict__ vT)
{
    const int m = blockIdx.x;
    const int t = m >> 2;
    const int b = m & 3;
    const size_t base = (size_t)m * (3 * E);

    for (int e = threadIdx.x; e < 3 * E; e += 256) {
        const int sec = e >> 10;
        const int r   = e & 1023;
        const int h   = r >> 6;
        const int d   = r & 63;
        const float val = qkv[base + e];
        const int bh = b * H + h;
        if (sec == 2) {
            vT[((size_t)bh * D + d) * T + t] = val;
        } else {
            const size_t oidx = (size_t)bh * T * D + (size_t)t * D + d;
            const float ang = pos[t * D + d];
            float c, s;
            sincosf(ang, &s, &c);
            const int pd = (d < 32) ? (e + 32) : (e - 32);
            const float other = qkv[base + pd];
            const float rot = (d < 32) ? -other : other;
            const float res = fmaf(val, c, rot * s);
            if (sec == 0) q[oidx] = res * 0.125f;
            else          k[oidx] = res;
        }
    }
}

// ---------------------------------------------------------------------------
// Row softmax over raw scores, in place, causal. Zero-fills masked region.
// ---------------------------------------------------------------------------
__global__ __launch_bounds__(256) void softmax_kernel(float* __restrict__ attn)
{
    const int t  = blockIdx.x;
    const int bh = blockIdx.y;
    float* rowp = attn + (size_t)bh * T * T + (size_t)t * T;
    const int L = t + 1;

    __shared__ float row[T];
    __shared__ float red[8];
    const int tid = threadIdx.x;

    float m = -1e30f;
    for (int i = tid; i < L; i += 256) {
        const float x = rowp[i];
        row[i] = x;
        m = fmaxf(m, x);
    }
#pragma unroll
    for (int o = 16; o; o >>= 1) m = fmaxf(m, __shfl_xor_sync(0xffffffffu, m, o));
    if ((tid & 31) == 0) red[tid >> 5] = m;
    __syncthreads();
    m = red[0];
#pragma unroll
    for (int w = 1; w < 8; w++) m = fmaxf(m, red[w]);

    float sum = 0.f;
    for (int i = tid; i < L; i += 256) {
        const float e = __expf(row[i] - m);
        row[i] = e;
        sum += e;
    }
#pragma unroll
    for (int o = 16; o; o >>= 1) sum += __shfl_xor_sync(0xffffffffu, sum, o);
    __syncthreads();
    if ((tid & 31) == 0) red[tid >> 5] = sum;
    __syncthreads();
    sum = 0.f;
#pragma unroll
    for (int w = 0; w < 8; w++) sum += red[w];
    const float inv = 1.f / sum;

    for (int i = tid; i < L; i += 256) rowp[i] = row[i] * inv;
    for (int i = L + tid; i < T; i += 256) rowp[i] = 0.f;
}

// ---------------------------------------------------------------------------
// Launch
// ---------------------------------------------------------------------------
extern "C" void kernel_launch(void* const* d_in, const int* in_sizes, int n_in,
                              void* d_out, int out_size)
{
    const float* input = (const float*)d_in[0];
    const float* pos   = (const float*)d_in[1];
    const float* in_w  = (const float*)d_in[2];
    const float* in_b  = (const float*)d_in[3];
    const float* out_w = (const float*)d_in[4];
    const float* out_b = (const float*)d_in[5];
    float* out = (float*)d_out;

    float *qkv, *q, *k, *vT, *ctx, *attn_scratch;
    cudaGetSymbolAddress((void**)&qkv,          g_qkv);
    cudaGetSymbolAddress((void**)&q,            g_q);
    cudaGetSymbolAddress((void**)&k,            g_k);
    cudaGetSymbolAddress((void**)&vT,           g_vT);
    cudaGetSymbolAddress((void**)&ctx,          g_ctx);
    cudaGetSymbolAddress((void**)&attn_scratch, g_attn);

    float* attn = ((size_t)out_size >= OUT_ELEMS + ATTN_ELEMS)
                      ? (out + OUT_ELEMS) : attn_scratch;

    // 1) fused QKV projection: [8192, 3072] = input[8192,1024] @ in_w^T + b
    mma_gemm<128><<<dim3(3 * E / 128, T * B / 128, 1), 256>>>(
        input, in_w, in_b, qkv, E, E, E, 3 * E, 0, 0, 0, 0);

    // 2) RoPE + reshape (q,k per-head; v transposed)
    rope_kernel<<<T * B, 256>>>(qkv, pos, q, k, vT);

    // 3) raw scores per head (causal tile skip): attn[bh][t][s] = q_t . k_s
    mma_gemm<128><<<dim3(T / 128, T / 128, BH), 256>>>(
        q, k, nullptr, attn, D, D, D, T,
        (size_t)T * D, (size_t)T * D, (size_t)T * T, 1);

    // 4) in-place causal softmax (+ zero masked region)
    softmax_kernel<<<dim3(T, BH), 256>>>(attn);

    // 5) ctx[t, bh*64+d] = sum_s attn[bh][t][s] * vT[bh][d][s]  (K bounded)
    mma_gemm<64><<<dim3(1, T / 128, BH), 256>>>(
        attn, vT, nullptr, ctx, T, T, T, B * E,
        (size_t)T * T, (size_t)D * T, (size_t)D, 2);

    // 6) output projection
    mma_gemm<128><<<dim3(E / 128, T * B / 128, 1), 256>>>(
        ctx, out_w, out_b, out, E, E, E, E, 0, 0, 0, 0);
}